// round 6
// baseline (speedup 1.0000x reference)
#include <cuda_runtime.h>
#include <math.h>

#define B_ 8
#define H_ 56
#define W_ 56
#define C_ 128
#define TOTPTS (B_*65536)
#define FEATTOT (B_*C_*H_*W_)
#define BD 384
#define PPB 768
#define GRID ((TOTPTS + PPB - 1) / PPB)

typedef unsigned long long u64;

// NHWC-transposed feature scratch (12.8 MB)
__device__ __align__(128) float g_feat_nhwc[FEATTOT];
// h1 scratch: [64 rows][TOTPTS] — written/read by the same thread, coalesced.
__device__ float g_h1[64 * TOTPTS];

__global__ void __launch_bounds__(256) transpose_kernel(const float* __restrict__ f) {
    int idx = blockIdx.x * 256 + threadIdx.x;
    if (idx >= FEATTOT) return;
    int c = idx & (C_ - 1);
    int rest = idx >> 7;
    int w = rest % W_;
    int r2 = rest / W_;
    int h = r2 % H_;
    int b = r2 / H_;
    g_feat_nhwc[idx] = f[((b * C_ + c) * H_ + h) * W_ + w];
}

__device__ __forceinline__ u64 pk2(float lo, float hi) {
    u64 r; asm("mov.b64 %0, {%1, %2};" : "=l"(r) : "f"(lo), "f"(hi)); return r;
}
__device__ __forceinline__ void upk2(u64 v, float& lo, float& hi) {
    asm("mov.b64 {%0, %1}, %2;" : "=f"(lo), "=f"(hi) : "l"(v));
}
__device__ __forceinline__ void fma2(u64& acc, u64 a, u64 b) {
    asm("fma.rn.f32x2 %0, %1, %2, %0;" : "+l"(acc) : "l"(a), "l"(b));
}
__device__ __forceinline__ u64 relu2(u64 v) {
    float lo, hi; upk2(v, lo, hi);
    return pk2(fmaxf(lo, 0.0f), fmaxf(hi, 0.0f));
}

// shared layout (float offsets)
#define OFF_W1   0        // 16384  W1 [256 rows][64]
#define OFF_W2   16384    // 4096
#define OFF_W3   20480    // 4096
#define OFF_W4   24576    // 64
#define OFF_B1   24640    // 64
#define OFF_B2   24704    // 64
#define OFF_B3   24768    // 64
#define OFF_BG4  24832    // 256 (64 x float4 padded Bg rows)
#define OFF_B4   25088    // 4
#define OFF_TBLW 25092    // 3072 (768 pts x 4 bilinear weights)
#define OFF_TBLB 28164    // 3072 (768 pts x 4 corner bases, int)
#define OFF_STG  31236    // 25344 (768 rows x 33) ; reused as hs [64][384] in tails
#define SMEM_FLOATS (OFF_STG + 25344)
#define SMEM_BYTES  (SMEM_FLOATS * 4)   // 226320 B

__device__ __forceinline__ void project_point(
    const float* __restrict__ points, const float* __restrict__ kmat,
    const float* __restrict__ rt, int pidx,
    float* tw, int* tb, float& opx, float& opy, float& opz)
{
    int b = pidx >> 16;
    float px = points[pidx*3 + 0];
    float py = points[pidx*3 + 1];
    float pz = points[pidx*3 + 2];
    opx = px; opy = py; opz = pz;
    const float* rtb = rt + b*12;
    const float* kb  = kmat + b*9;
    float c0 = rtb[0]*px + rtb[1]*py + rtb[2]*pz + rtb[3];
    float c1 = rtb[4]*px + rtb[5]*py + rtb[6]*pz + rtb[7];
    float c2 = rtb[8]*px + rtb[9]*py + rtb[10]*pz + rtb[11];
    float i0 = kb[0]*c0 + kb[1]*c1 + kb[2]*c2;
    float i1 = kb[3]*c0 + kb[4]*c1 + kb[5]*c2;
    float i2 = kb[6]*c0 + kb[7]*c1 + kb[8]*c2;
    float zb = i2 + 1e-8f;
    float u = i0 / zb, v = i1 / zb;
    float validf = (i2 > 0.0f) ? 1.0f : 0.0f;
    float un = (2.0f*u + 1.0f) / 56.0f - 1.0f;
    float vn = (2.0f*v + 1.0f) / 56.0f - 1.0f;
    float xp = ((un + 1.0f) * 56.0f - 1.0f) * 0.5f;
    float yp = ((vn + 1.0f) * 56.0f - 1.0f) * 0.5f;
    float x0f = floorf(xp), y0f = floorf(yp);
    float fx = xp - x0f, fy = yp - y0f;
    float gx0 = 1.0f - fx, gy0 = 1.0f - fy;
    int ix0 = (int)x0f, iy0 = (int)y0f;
    int ix1 = ix0 + 1, iy1 = iy0 + 1;
    float m00 = (ix0 >= 0 && ix0 < W_ && iy0 >= 0 && iy0 < H_) ? validf : 0.0f;
    float m10 = (ix1 >= 0 && ix1 < W_ && iy0 >= 0 && iy0 < H_) ? validf : 0.0f;
    float m01 = (ix0 >= 0 && ix0 < W_ && iy1 >= 0 && iy1 < H_) ? validf : 0.0f;
    float m11 = (ix1 >= 0 && ix1 < W_ && iy1 >= 0 && iy1 < H_) ? validf : 0.0f;
    tw[0] = gx0*gy0*m00; tw[1] = fx*gy0*m10; tw[2] = gx0*fy*m01; tw[3] = fx*fy*m11;
    int cx0 = min(max(ix0, 0), W_-1), cx1 = min(max(ix1, 0), W_-1);
    int cy0 = min(max(iy0, 0), H_-1), cy1 = min(max(iy1, 0), H_-1);
    tb[0] = ((b*H_ + cy0)*W_ + cx0) << 7;
    tb[1] = ((b*H_ + cy0)*W_ + cx1) << 7;
    tb[2] = ((b*H_ + cy1)*W_ + cx0) << 7;
    tb[3] = ((b*H_ + cy1)*W_ + cx1) << 7;
}

// layers 2..4 for one point; h1 read from g_h1 column pt; h2 via hs columns.
__device__ __forceinline__ float mlp_tail(const float* __restrict__ s,
                                          int pt, float* __restrict__ hs, int tid) {
    u64 acc[32];
    {
        const ulonglong2* bp = (const ulonglong2*)(s + OFF_B2);
        #pragma unroll
        for (int t = 0; t < 16; t++) { ulonglong2 v = bp[t]; acc[2*t] = v.x; acc[2*t+1] = v.y; }
    }
    const float* gh = g_h1 + pt;
    #pragma unroll 4
    for (int i = 0; i < 64; i++) {
        float hv = gh[i*TOTPTS];
        u64 d = pk2(hv, hv);
        const ulonglong2* wr = (const ulonglong2*)(s + OFF_W2 + i*64);
        #pragma unroll
        for (int t = 0; t < 16; t++) {
            ulonglong2 w = wr[t];
            fma2(acc[2*t], d, w.x); fma2(acc[2*t+1], d, w.y);
        }
    }
    #pragma unroll
    for (int t = 0; t < 32; t++) {
        float lo, hi; upk2(relu2(acc[t]), lo, hi);
        hs[(2*t)*BD + tid] = lo; hs[(2*t+1)*BD + tid] = hi;
    }
    u64 acc3[32];
    {
        const ulonglong2* bp = (const ulonglong2*)(s + OFF_B3);
        #pragma unroll
        for (int t = 0; t < 16; t++) { ulonglong2 v = bp[t]; acc3[2*t] = v.x; acc3[2*t+1] = v.y; }
    }
    #pragma unroll 1
    for (int i = 0; i < 64; i++) {
        float hv = hs[i*BD + tid];
        u64 d = pk2(hv, hv);
        const ulonglong2* wr = (const ulonglong2*)(s + OFF_W3 + i*64);
        #pragma unroll
        for (int t = 0; t < 16; t++) {
            ulonglong2 w = wr[t];
            fma2(acc3[2*t], d, w.x); fma2(acc3[2*t+1], d, w.y);
        }
    }
    float o = s[OFF_B4];
    #pragma unroll
    for (int t = 0; t < 32; t++) {
        float lo, hi; upk2(acc3[t], lo, hi);
        o = fmaf(fmaxf(lo, 0.0f), s[OFF_W4 + 2*t],   o);
        o = fmaf(fmaxf(hi, 0.0f), s[OFF_W4 + 2*t+1], o);
    }
    return o;
}

__global__ void __launch_bounds__(BD) decoder_kernel(
    const float* __restrict__ points, const float* __restrict__ kmat,
    const float* __restrict__ rt, const float* __restrict__ Bg,
    const float* __restrict__ W1, const float* __restrict__ b1,
    const float* __restrict__ W2, const float* __restrict__ b2,
    const float* __restrict__ W3, const float* __restrict__ b3,
    const float* __restrict__ W4, const float* __restrict__ b4,
    float* __restrict__ out)
{
    extern __shared__ __align__(16) float s[];
    int tid = threadIdx.x;

    // ---- stage weights ----
    for (int t = tid; t < 16384; t += BD) s[OFF_W1 + t] = W1[t];
    for (int t = tid; t < 4096; t += BD) { s[OFF_W2 + t] = W2[t]; s[OFF_W3 + t] = W3[t]; }
    if (tid < 64) {
        s[OFF_W4 + tid] = W4[tid]; s[OFF_B1 + tid] = b1[tid];
        s[OFF_B2 + tid] = b2[tid]; s[OFF_B3 + tid] = b3[tid];
        s[OFF_BG4 + tid*4 + 0] = Bg[tid*3 + 0];
        s[OFF_BG4 + tid*4 + 1] = Bg[tid*3 + 1];
        s[OFF_BG4 + tid*4 + 2] = Bg[tid*3 + 2];
        s[OFF_BG4 + tid*4 + 3] = 0.0f;
    }
    if (tid == 0) s[OFF_B4] = b4[0];

    int base = blockIdx.x * PPB;
    int pA = min(base + tid, TOTPTS - 1);
    int pB = min(base + BD + tid, TOTPTS - 1);
    float pxA, pyA, pzA, pxB, pyB, pzB;
    project_point(points, kmat, rt, pA, s + OFF_TBLW + tid*4,
                  (int*)s + OFF_TBLB + tid*4, pxA, pyA, pzA);
    project_point(points, kmat, rt, pB, s + OFF_TBLW + (BD + tid)*4,
                  (int*)s + OFF_TBLB + (BD + tid)*4, pxB, pyB, pzB);
    __syncthreads();

    const float* tw = s + OFF_TBLW;
    const int*   tb = (const int*)s + OFF_TBLB;
    float* stg = s + OFF_STG;

    // ---- layer 1 in two output-half passes (32 outputs x 2 pts = 32 u64 accs) ----
    #pragma unroll 1
    for (int half = 0; half < 2; half++) {
        u64 accA[16], accB[16];
        {
            const ulonglong2* bp = (const ulonglong2*)(s + OFF_B1 + half*32);
            #pragma unroll
            for (int t = 0; t < 8; t++) {
                ulonglong2 v = bp[t];
                accA[2*t] = v.x; accA[2*t+1] = v.y;
                accB[2*t] = v.x; accB[2*t+1] = v.y;
            }
        }

        // image features: 4 quarters of 32 channels, gathered fresh per half
        #pragma unroll 1
        for (int q = 0; q < 4; q++) {
            #pragma unroll 2
            for (int i = 0; i < 16; i++) {
                int task = i*BD + tid;          // 0..6143
                int p = task >> 3, c = task & 7;
                float4 wv = *(const float4*)(tw + p*4);
                int4   bv = *(const int4*)(tb + p*4);
                int off = q*32 + c*4;
                float4 v0 = *(const float4*)(g_feat_nhwc + bv.x + off);
                float4 v1 = *(const float4*)(g_feat_nhwc + bv.y + off);
                float4 v2 = *(const float4*)(g_feat_nhwc + bv.z + off);
                float4 v3 = *(const float4*)(g_feat_nhwc + bv.w + off);
                float ax = wv.x*v0.x + wv.y*v1.x + wv.z*v2.x + wv.w*v3.x;
                float ay = wv.x*v0.y + wv.y*v1.y + wv.z*v2.y + wv.w*v3.y;
                float az = wv.x*v0.z + wv.y*v1.z + wv.z*v2.z + wv.w*v3.z;
                float aw = wv.x*v0.w + wv.y*v1.w + wv.z*v2.w + wv.w*v3.w;
                float* dst = stg + p*33 + c*4;
                dst[0] = ax; dst[1] = ay; dst[2] = az; dst[3] = aw;
            }
            __syncthreads();
            #pragma unroll 1
            for (int c2 = 0; c2 < 32; c2++) {
                float fA = stg[tid*33 + c2];
                float fB = stg[(BD + tid)*33 + c2];
                u64 dA = pk2(fA, fA), dB = pk2(fB, fB);
                const ulonglong2* wr =
                    (const ulonglong2*)(s + OFF_W1 + (q*32 + c2)*64 + half*32);
                #pragma unroll
                for (int t = 0; t < 8; t++) {
                    ulonglong2 w = wr[t];
                    fma2(accA[2*t], dA, w.x); fma2(accA[2*t+1], dA, w.y);
                    fma2(accB[2*t], dB, w.x); fma2(accB[2*t+1], dB, w.y);
                }
            }
            __syncthreads();
        }

        // Fourier features (recomputed per half)
        #pragma unroll 1
        for (int m = 0; m < 64; m++) {
            float4 bg = *(const float4*)(s + OFF_BG4 + m*4);
            float sA, cA, sB, cB;
            sincosf(6.28318530717958647692f * (pxA*bg.x + pyA*bg.y + pzA*bg.z), &sA, &cA);
            sincosf(6.28318530717958647692f * (pxB*bg.x + pyB*bg.y + pzB*bg.z), &sB, &cB);
            u64 dsA = pk2(sA, sA), dcA = pk2(cA, cA);
            u64 dsB = pk2(sB, sB), dcB = pk2(cB, cB);
            const ulonglong2* wrs =
                (const ulonglong2*)(s + OFF_W1 + (128 + m)*64 + half*32);
            const ulonglong2* wrc =
                (const ulonglong2*)(s + OFF_W1 + (192 + m)*64 + half*32);
            #pragma unroll
            for (int t = 0; t < 8; t++) {
                ulonglong2 w = wrs[t];
                fma2(accA[2*t], dsA, w.x); fma2(accA[2*t+1], dsA, w.y);
                fma2(accB[2*t], dsB, w.x); fma2(accB[2*t+1], dsB, w.y);
            }
            #pragma unroll
            for (int t = 0; t < 8; t++) {
                ulonglong2 w = wrc[t];
                fma2(accA[2*t], dcA, w.x); fma2(accA[2*t+1], dcA, w.y);
                fma2(accB[2*t], dcB, w.x); fma2(accB[2*t+1], dcB, w.y);
            }
        }

        // relu -> h1 rows [half*32 .. half*32+31] in global scratch (coalesced)
        #pragma unroll
        for (int t = 0; t < 16; t++) {
            float lo, hi;
            upk2(relu2(accA[t]), lo, hi);
            g_h1[(half*32 + 2*t)*TOTPTS + pA]     = lo;
            g_h1[(half*32 + 2*t + 1)*TOTPTS + pA] = hi;
            upk2(relu2(accB[t]), lo, hi);
            g_h1[(half*32 + 2*t)*TOTPTS + pB]     = lo;
            g_h1[(half*32 + 2*t + 1)*TOTPTS + pB] = hi;
        }
    }

    // ---- tails: stg region is free now; per-thread columns only, no syncs ----
    float outA = mlp_tail(s, pA, stg, tid);
    float outB = mlp_tail(s, pB, stg, tid);

    if (base + tid < TOTPTS)      out[pA] = outA;
    if (base + BD + tid < TOTPTS) out[pB] = outB;
}

extern "C" void kernel_launch(void* const* d_in, const int* in_sizes, int n_in,
                              void* d_out, int out_size) {
    const float* features = (const float*)d_in[0];
    const float* points   = (const float*)d_in[1];
    const float* kmat     = (const float*)d_in[2];
    const float* rt       = (const float*)d_in[3];
    const float* Bg       = (const float*)d_in[4];
    const float* W1       = (const float*)d_in[5];
    const float* b1       = (const float*)d_in[6];
    const float* W2       = (const float*)d_in[7];
    const float* b2       = (const float*)d_in[8];
    const float* W3       = (const float*)d_in[9];
    const float* b3       = (const float*)d_in[10];
    const float* W4       = (const float*)d_in[11];
    const float* b4       = (const float*)d_in[12];
    float* out = (float*)d_out;

    transpose_kernel<<<FEATTOT/256, 256>>>(features);

    cudaFuncSetAttribute(decoder_kernel,
                         cudaFuncAttributeMaxDynamicSharedMemorySize, SMEM_BYTES);
    decoder_kernel<<<GRID, BD, SMEM_BYTES>>>(
        points, kmat, rt, Bg, W1, b1, W2, b2, W3, b3, W4, b4, out);
}

// round 8
// speedup vs baseline: 2.8931x; 2.8931x over previous
#include <cuda_runtime.h>
#include <cuda_bf16.h>
#include <math.h>

#define B_ 8
#define H_ 56
#define W_ 56
#define TOTPTS (B_*65536)
#define FEATTOT (B_*128*H_*W_)
#define BD 384
#define NWARP 12
#define TILE_PTS 192
#define NT ((TOTPTS + TILE_PTS - 1) / TILE_PTS)
#define GRID_DEC 152
#define TWOPI 6.28318530717958647692f

// smem byte offsets
#define SB_W1HI 0
#define SB_W1LO 32768
#define SB_W2HI 65536
#define SB_W2LO 73728
#define SB_W3HI 81920
#define SB_W3LO 90112
#define SB_A1HI 98304
#define SB_A1LO 147456
#define SB_B1   196608
#define SB_B2   196864
#define SB_B3   197120
#define SB_W4   197376
#define SB_BG   197632
#define SB_B4   198656
#define SB_TBLW 198672
#define SB_TBLB 201744
#define SB_TBLP 204816
#define SMEM_BYTES 207888

__device__ __align__(128) float g_feat_nhwc[FEATTOT];

__global__ void __launch_bounds__(256) transpose_kernel(const float* __restrict__ f) {
    int idx = blockIdx.x * 256 + threadIdx.x;
    if (idx >= FEATTOT) return;
    int c = idx & 127;
    int rest = idx >> 7;
    int w = rest % W_;
    int r2 = rest / W_;
    int h = r2 % H_;
    int b = r2 / H_;
    g_feat_nhwc[idx] = f[((b * 128 + c) * H_ + h) * W_ + w];
}

__device__ __forceinline__ unsigned smem_u32(const void* p) {
    unsigned a;
    asm("{ .reg .u64 t; cvta.to.shared.u64 t, %1; cvt.u32.u64 %0, t; }" : "=r"(a) : "l"(p));
    return a;
}
__device__ __forceinline__ void ldsm4(unsigned& r0, unsigned& r1, unsigned& r2, unsigned& r3,
                                      unsigned addr) {
    asm volatile("ldmatrix.sync.aligned.m8n8.x4.shared.b16 {%0,%1,%2,%3}, [%4];"
                 : "=r"(r0), "=r"(r1), "=r"(r2), "=r"(r3) : "r"(addr));
}
__device__ __forceinline__ void mma16816(float* c, unsigned a0, unsigned a1, unsigned a2,
                                         unsigned a3, unsigned b0, unsigned b1) {
    asm volatile("mma.sync.aligned.m16n8k16.row.col.f32.bf16.bf16.f32 "
                 "{%0,%1,%2,%3}, {%4,%5,%6,%7}, {%8,%9}, {%0,%1,%2,%3};"
                 : "+f"(c[0]), "+f"(c[1]), "+f"(c[2]), "+f"(c[3])
                 : "r"(a0), "r"(a1), "r"(a2), "r"(a3), "r"(b0), "r"(b1));
}
// split pair of floats into bf16x2 hi + bf16x2 lo (residual)
__device__ __forceinline__ void split2(float a, float b, unsigned& hi, unsigned& lo) {
    __nv_bfloat16 ha = __float2bfloat16(a), hb = __float2bfloat16(b);
    __nv_bfloat162 hp(ha, hb);
    __nv_bfloat162 lp(__float2bfloat16(a - __bfloat162float(ha)),
                      __float2bfloat16(b - __bfloat162float(hb)));
    hi = *(unsigned*)&hp;
    lo = *(unsigned*)&lp;
}
__device__ __forceinline__ void initc(float (*c)[4], const float* bias, int lane) {
    int cq = (lane & 3) * 2;
    #pragma unroll
    for (int j = 0; j < 8; j++) {
        float b0 = bias[j*8 + cq], b1v = bias[j*8 + cq + 1];
        c[j][0] = b0; c[j][1] = b1v; c[j][2] = b0; c[j][3] = b1v;
    }
}
// relu + split + store 16x64 A2 tile (row stride 256B, chunk^row swizzle)
__device__ __forceinline__ void relu_store_A2(float (*c)[4], char* sc,
                                              unsigned aHiOff, unsigned aLoOff, int lane) {
    int r = lane >> 2, cq = (lane & 3) * 2;
    #pragma unroll
    for (int j = 0; j < 8; j++) {
        float v0 = fmaxf(c[j][0], 0.f), v1 = fmaxf(c[j][1], 0.f);
        float v2 = fmaxf(c[j][2], 0.f), v3 = fmaxf(c[j][3], 0.f);
        unsigned h01, l01, h23, l23;
        split2(v0, v1, h01, l01);
        split2(v2, v3, h23, l23);
        unsigned off0 = (unsigned)(r*256 + ((j ^ r) * 16) + cq*2);
        unsigned off1 = off0 + 8*256;
        *(unsigned*)(sc + aHiOff + off0) = h01;
        *(unsigned*)(sc + aLoOff + off0) = l01;
        *(unsigned*)(sc + aHiOff + off1) = h23;
        *(unsigned*)(sc + aLoOff + off1) = l23;
    }
}
// one 64-K GEMM layer: A 16x64 (stride 256B) @ B 64x64 (rows 128B) -> C
__device__ __forceinline__ void gemm64(float (*c)[4], unsigned aHiA, unsigned aLoA,
                                       unsigned bHiA, unsigned bLoA, int lane) {
    int r = lane & 15, kh = lane >> 4;
    int l7 = lane & 7, mat = lane >> 3;
    int khb = mat & 1, jup = (mat >> 1) & 1;
    #pragma unroll 2
    for (int kc = 0; kc < 4; kc++) {
        unsigned ac = (unsigned)(kc*2 + kh);
        unsigned aoff = (unsigned)(r*256) + ((ac ^ (unsigned)(r & 7)) * 16u);
        unsigned ah0, ah1, ah2, ah3, al0, al1, al2, al3;
        ldsm4(ah0, ah1, ah2, ah3, aHiA + aoff);
        ldsm4(al0, al1, al2, al3, aLoA + aoff);
        #pragma unroll
        for (int jp = 0; jp < 4; jp++) {
            int n = (jp*2 + jup)*8 + l7;
            unsigned bc = (unsigned)(kc*2 + khb);
            unsigned boff = (unsigned)(n*128) + ((bc ^ (unsigned)(n & 7)) * 16u);
            unsigned bh0, bh1, bh2, bh3, bl0, bl1, bl2, bl3;
            ldsm4(bh0, bh1, bh2, bh3, bHiA + boff);
            ldsm4(bl0, bl1, bl2, bl3, bLoA + boff);
            mma16816(c[jp*2],   ah0, ah1, ah2, ah3, bh0, bh1);
            mma16816(c[jp*2],   al0, al1, al2, al3, bh0, bh1);
            mma16816(c[jp*2],   ah0, ah1, ah2, ah3, bl0, bl1);
            mma16816(c[jp*2+1], ah0, ah1, ah2, ah3, bh2, bh3);
            mma16816(c[jp*2+1], al0, al1, al2, al3, bh2, bh3);
            mma16816(c[jp*2+1], ah0, ah1, ah2, ah3, bl2, bl3);
        }
    }
}
// layer-1 half: A 16x128 (stride 256B) @ W1[64][256] rows 512B, k base = kbase
__device__ __forceinline__ void gemmW1(float (*c)[4], unsigned aHiA, unsigned aLoA,
                                       unsigned bHiA, unsigned bLoA, int kbase, int lane) {
    int r = lane & 15, kh = lane >> 4;
    int l7 = lane & 7, mat = lane >> 3;
    int khb = mat & 1, jup = (mat >> 1) & 1;
    #pragma unroll 2
    for (int kc = 0; kc < 8; kc++) {
        unsigned ac = (unsigned)(kc*2 + kh);
        unsigned aoff = (unsigned)(r*256) + ((ac ^ (unsigned)(r & 7)) * 16u);
        unsigned ah0, ah1, ah2, ah3, al0, al1, al2, al3;
        ldsm4(ah0, ah1, ah2, ah3, aHiA + aoff);
        ldsm4(al0, al1, al2, al3, aLoA + aoff);
        #pragma unroll
        for (int jp = 0; jp < 4; jp++) {
            int n = (jp*2 + jup)*8 + l7;
            unsigned bc = (unsigned)((kbase >> 3) + kc*2 + khb);  // up to 31
            unsigned boff = (unsigned)(n*512) + ((bc ^ (unsigned)(n & 7)) * 16u);
            unsigned bh0, bh1, bh2, bh3, bl0, bl1, bl2, bl3;
            ldsm4(bh0, bh1, bh2, bh3, bHiA + boff);
            ldsm4(bl0, bl1, bl2, bl3, bLoA + boff);
            mma16816(c[jp*2],   ah0, ah1, ah2, ah3, bh0, bh1);
            mma16816(c[jp*2],   al0, al1, al2, al3, bh0, bh1);
            mma16816(c[jp*2],   ah0, ah1, ah2, ah3, bl0, bl1);
            mma16816(c[jp*2+1], ah0, ah1, ah2, ah3, bh2, bh3);
            mma16816(c[jp*2+1], al0, al1, al2, al3, bh2, bh3);
            mma16816(c[jp*2+1], ah0, ah1, ah2, ah3, bl2, bl3);
        }
    }
}

__global__ void __launch_bounds__(BD) decoder_kernel(
    const float* __restrict__ points, const float* __restrict__ kmat,
    const float* __restrict__ rt, const float* __restrict__ Bg,
    const float* __restrict__ W1, const float* __restrict__ b1,
    const float* __restrict__ W2, const float* __restrict__ b2,
    const float* __restrict__ W3, const float* __restrict__ b3,
    const float* __restrict__ W4, const float* __restrict__ b4,
    float* __restrict__ out)
{
    extern __shared__ __align__(16) char sc[];
    unsigned sb = smem_u32(sc);
    int tid = threadIdx.x;
    int lane = tid & 31, wid = tid >> 5;

    // ---- stage weights: smem layout [n][k] (k contiguous), hi/lo bf16, chunk^n swizzle ----
    for (int t = tid; t < 16384; t += BD) {
        int k = t >> 6, n = t & 63;
        float v = W1[t];
        __nv_bfloat16 hv = __float2bfloat16(v);
        __nv_bfloat16 lv = __float2bfloat16(v - __bfloat162float(hv));
        unsigned off = (unsigned)(n*512) + ((((unsigned)(k >> 3)) ^ (unsigned)(n & 7)) * 16u)
                     + (unsigned)((k & 7) * 2);
        *(__nv_bfloat16*)(sc + SB_W1HI + off) = hv;
        *(__nv_bfloat16*)(sc + SB_W1LO + off) = lv;
    }
    for (int t = tid; t < 4096; t += BD) {
        int k = t >> 6, n = t & 63;
        unsigned off = (unsigned)(n*128) + ((((unsigned)(k >> 3)) ^ (unsigned)(n & 7)) * 16u)
                     + (unsigned)((k & 7) * 2);
        float v2 = W2[t];
        __nv_bfloat16 h2 = __float2bfloat16(v2);
        *(__nv_bfloat16*)(sc + SB_W2HI + off) = h2;
        *(__nv_bfloat16*)(sc + SB_W2LO + off) = __float2bfloat16(v2 - __bfloat162float(h2));
        float v3 = W3[t];
        __nv_bfloat16 h3 = __float2bfloat16(v3);
        *(__nv_bfloat16*)(sc + SB_W3HI + off) = h3;
        *(__nv_bfloat16*)(sc + SB_W3LO + off) = __float2bfloat16(v3 - __bfloat162float(h3));
    }
    if (tid < 64) {
        ((float*)(sc + SB_B1))[tid] = b1[tid];
        ((float*)(sc + SB_B2))[tid] = b2[tid];
        ((float*)(sc + SB_B3))[tid] = b3[tid];
        ((float*)(sc + SB_W4))[tid] = W4[tid];
        ((float*)(sc + SB_BG))[tid*4 + 0] = Bg[tid*3 + 0];
        ((float*)(sc + SB_BG))[tid*4 + 1] = Bg[tid*3 + 1];
        ((float*)(sc + SB_BG))[tid*4 + 2] = Bg[tid*3 + 2];
        ((float*)(sc + SB_BG))[tid*4 + 3] = 0.0f;
    }
    if (tid == 0) *(float*)(sc + SB_B4) = b4[0];
    __syncthreads();

    const float* b1p = (const float*)(sc + SB_B1);
    const float* b2p = (const float*)(sc + SB_B2);
    const float* b3p = (const float*)(sc + SB_B3);
    const float* w4p = (const float*)(sc + SB_W4);
    float b4v = *(const float*)(sc + SB_B4);

    unsigned aHiOff = SB_A1HI + (unsigned)(wid * 4096);
    unsigned aLoOff = SB_A1LO + (unsigned)(wid * 4096);
    unsigned aHiA = sb + aHiOff, aLoA = sb + aLoOff;
    unsigned twOff = SB_TBLW + (unsigned)(wid * 256);
    unsigned tbOff = SB_TBLB + (unsigned)(wid * 256);
    unsigned tpOff = SB_TBLP + (unsigned)(wid * 256);

    for (int tile = blockIdx.x; tile < NT; tile += GRID_DEC) {
        int p0 = tile * TILE_PTS + wid * 16;

        // ---- 1. projection (lanes 0..15), per-warp tables ----
        if (lane < 16) {
            int pidx = min(p0 + lane, TOTPTS - 1);
            int b = pidx >> 16;
            float px = points[pidx*3 + 0];
            float py = points[pidx*3 + 1];
            float pz = points[pidx*3 + 2];
            const float* rtb = rt + b*12;
            const float* kb  = kmat + b*9;
            float c0 = rtb[0]*px + rtb[1]*py + rtb[2]*pz + rtb[3];
            float c1 = rtb[4]*px + rtb[5]*py + rtb[6]*pz + rtb[7];
            float c2 = rtb[8]*px + rtb[9]*py + rtb[10]*pz + rtb[11];
            float i0 = kb[0]*c0 + kb[1]*c1 + kb[2]*c2;
            float i1 = kb[3]*c0 + kb[4]*c1 + kb[5]*c2;
            float i2 = kb[6]*c0 + kb[7]*c1 + kb[8]*c2;
            float zb = i2 + 1e-8f;
            float u = i0 / zb, v = i1 / zb;
            float validf = (i2 > 0.0f) ? 1.0f : 0.0f;
            float un = (2.0f*u + 1.0f) / 56.0f - 1.0f;
            float vn = (2.0f*v + 1.0f) / 56.0f - 1.0f;
            float xp = ((un + 1.0f) * 56.0f - 1.0f) * 0.5f;
            float yp = ((vn + 1.0f) * 56.0f - 1.0f) * 0.5f;
            float x0f = floorf(xp), y0f = floorf(yp);
            float fx = xp - x0f, fy = yp - y0f;
            float gx0 = 1.0f - fx, gy0 = 1.0f - fy;
            int ix0 = (int)x0f, iy0 = (int)y0f;
            int ix1 = ix0 + 1, iy1 = iy0 + 1;
            float m00 = (ix0 >= 0 && ix0 < W_ && iy0 >= 0 && iy0 < H_) ? validf : 0.0f;
            float m10 = (ix1 >= 0 && ix1 < W_ && iy0 >= 0 && iy0 < H_) ? validf : 0.0f;
            float m01 = (ix0 >= 0 && ix0 < W_ && iy1 >= 0 && iy1 < H_) ? validf : 0.0f;
            float m11 = (ix1 >= 0 && ix1 < W_ && iy1 >= 0 && iy1 < H_) ? validf : 0.0f;
            int cx0 = min(max(ix0, 0), W_-1), cx1 = min(max(ix1, 0), W_-1);
            int cy0 = min(max(iy0, 0), H_-1), cy1 = min(max(iy1, 0), H_-1);
            *(float4*)(sc + twOff + lane*16) =
                make_float4(gx0*gy0*m00, fx*gy0*m10, gx0*fy*m01, fx*fy*m11);
            *(int4*)(sc + tbOff + lane*16) =
                make_int4(((b*H_ + cy0)*W_ + cx0) << 7, ((b*H_ + cy0)*W_ + cx1) << 7,
                          ((b*H_ + cy1)*W_ + cx0) << 7, ((b*H_ + cy1)*W_ + cx1) << 7);
            *(float4*)(sc + tpOff + lane*16) = make_float4(px, py, pz, 0.0f);
        }
        __syncwarp();

        // ---- 2. gather image feats -> A1 (k 0..127); lane = float4 chunk of 512B row ----
        {
            int chunk = lane >> 1, sub8 = (lane & 1) * 8;
            #pragma unroll 2
            for (int p = 0; p < 16; p++) {
                float4 wv = *(const float4*)(sc + twOff + p*16);
                int4 bv = *(const int4*)(sc + tbOff + p*16);
                float4 v0 = *(const float4*)(g_feat_nhwc + bv.x + lane*4);
                float4 v1 = *(const float4*)(g_feat_nhwc + bv.y + lane*4);
                float4 v2 = *(const float4*)(g_feat_nhwc + bv.z + lane*4);
                float4 v3 = *(const float4*)(g_feat_nhwc + bv.w + lane*4);
                float a0 = wv.x*v0.x + wv.y*v1.x + wv.z*v2.x + wv.w*v3.x;
                float a1 = wv.x*v0.y + wv.y*v1.y + wv.z*v2.y + wv.w*v3.y;
                float a2 = wv.x*v0.z + wv.y*v1.z + wv.z*v2.z + wv.w*v3.z;
                float a3 = wv.x*v0.w + wv.y*v1.w + wv.z*v2.w + wv.w*v3.w;
                unsigned h01, l01, h23, l23;
                split2(a0, a1, h01, l01);
                split2(a2, a3, h23, l23);
                unsigned off = (unsigned)(p*256 + ((chunk ^ (p & 7)) * 16) + sub8);
                *(uint2*)(sc + aHiOff + off) = make_uint2(h01, h23);
                *(uint2*)(sc + aLoOff + off) = make_uint2(l01, l23);
            }
        }
        __syncwarp();

        // ---- layer 1 ----
        float c[8][4];
        initc(c, b1p, lane);
        gemmW1(c, aHiA, aLoA, sb + SB_W1HI, sb + SB_W1LO, 0, lane);
        __syncwarp();

        // ---- 3. fourier feats -> A1 (sin: local col m, cos: local col 64+m) ----
        #pragma unroll 4
        for (int it = 0; it < 32; it++) {
            int p = it >> 1, m = ((it & 1) << 5) + lane;
            float4 pc = *(const float4*)(sc + tpOff + p*16);
            float4 bg = *(const float4*)(sc + SB_BG + m*16);
            float dot = pc.x*bg.x + pc.y*bg.y + pc.z*bg.z;
            float sv, cv;
            sincosf(TWOPI * dot, &sv, &cv);
            __nv_bfloat16 sh = __float2bfloat16(sv);
            __nv_bfloat16 sl = __float2bfloat16(sv - __bfloat162float(sh));
            __nv_bfloat16 ch = __float2bfloat16(cv);
            __nv_bfloat16 cl = __float2bfloat16(cv - __bfloat162float(ch));
            unsigned key = (unsigned)(p & 7);
            unsigned offs = (unsigned)(p*256) + ((((unsigned)(m >> 3)) ^ key) * 16u)
                          + (unsigned)((m & 7) * 2);
            unsigned offc = (unsigned)(p*256) + ((((unsigned)((m >> 3) + 8)) ^ key) * 16u)
                          + (unsigned)((m & 7) * 2);
            *(__nv_bfloat16*)(sc + aHiOff + offs) = sh;
            *(__nv_bfloat16*)(sc + aLoOff + offs) = sl;
            *(__nv_bfloat16*)(sc + aHiOff + offc) = ch;
            *(__nv_bfloat16*)(sc + aLoOff + offc) = cl;
        }
        __syncwarp();
        gemmW1(c, aHiA, aLoA, sb + SB_W1HI, sb + SB_W1LO, 128, lane);
        __syncwarp();

        // ---- epilogue 1 -> A2, layer 2 ----
        relu_store_A2(c, sc, aHiOff, aLoOff, lane);
        __syncwarp();
        initc(c, b2p, lane);
        gemm64(c, aHiA, aLoA, sb + SB_W2HI, sb + SB_W2LO, lane);
        __syncwarp();

        // ---- epilogue 2 -> A2, layer 3 ----
        relu_store_A2(c, sc, aHiOff, aLoOff, lane);
        __syncwarp();
        initc(c, b3p, lane);
        gemm64(c, aHiA, aLoA, sb + SB_W3HI, sb + SB_W3LO, lane);

        // ---- layer 4: dot(relu(h3), W4) + b4, reduce across lane quads ----
        {
            int r = lane >> 2, cq = (lane & 3) * 2;
            float o0 = 0.f, o1 = 0.f;
            #pragma unroll
            for (int j = 0; j < 8; j++) {
                int col = j*8 + cq;
                float wa = w4p[col], wb = w4p[col + 1];
                o0 += fmaxf(c[j][0], 0.f) * wa + fmaxf(c[j][1], 0.f) * wb;
                o1 += fmaxf(c[j][2], 0.f) * wa + fmaxf(c[j][3], 0.f) * wb;
            }
            o0 += __shfl_xor_sync(0xFFFFFFFFu, o0, 1);
            o0 += __shfl_xor_sync(0xFFFFFFFFu, o0, 2);
            o1 += __shfl_xor_sync(0xFFFFFFFFu, o1, 1);
            o1 += __shfl_xor_sync(0xFFFFFFFFu, o1, 2);
            if ((lane & 3) == 0) {
                int pr = p0 + r;
                if (pr < TOTPTS)     out[pr]     = o0 + b4v;
                if (pr + 8 < TOTPTS) out[pr + 8] = o1 + b4v;
            }
        }
        __syncwarp();
    }
}

extern "C" void kernel_launch(void* const* d_in, const int* in_sizes, int n_in,
                              void* d_out, int out_size) {
    const float* features = (const float*)d_in[0];
    const float* points   = (const float*)d_in[1];
    const float* kmat     = (const float*)d_in[2];
    const float* rt       = (const float*)d_in[3];
    const float* Bg       = (const float*)d_in[4];
    const float* W1       = (const float*)d_in[5];
    const float* b1       = (const float*)d_in[6];
    const float* W2       = (const float*)d_in[7];
    const float* b2       = (const float*)d_in[8];
    const float* W3       = (const float*)d_in[9];
    const float* b3       = (const float*)d_in[10];
    const float* W4       = (const float*)d_in[11];
    const float* b4       = (const float*)d_in[12];
    float* out = (float*)d_out;

    transpose_kernel<<<FEATTOT/256, 256>>>(features);

    cudaFuncSetAttribute(decoder_kernel,
                         cudaFuncAttributeMaxDynamicSharedMemorySize, SMEM_BYTES);
    decoder_kernel<<<GRID_DEC, BD, SMEM_BYTES>>>(
        points, kmat, rt, Bg, W1, b1, W2, b2, W3, b3, W4, b4, out);
}

// round 10
// speedup vs baseline: 3.4716x; 1.2000x over previous
#include <cuda_runtime.h>
#include <cuda_bf16.h>
#include <math.h>

#define B_ 8
#define H_ 56
#define W_ 56
#define TOTPTS (B_*65536)
#define FEATTOT (B_*128*H_*W_)
#define BD 384
#define TILE_PTS 384
#define NT ((TOTPTS + TILE_PTS - 1) / TILE_PTS)
#define GRID_DEC 152
#define TWOPI 6.28318530717958647692f

// smem byte offsets
#define SB_W1HI 0
#define SB_W1LO 32768
#define SB_W2HI 65536
#define SB_W2LO 73728
#define SB_W3HI 81920
#define SB_W3LO 90112
#define SB_A1HI 98304
#define SB_A1LO 147456
#define SB_B1   196608
#define SB_B2   196864
#define SB_B3   197120
#define SB_W4   197376
#define SB_BG   197632
#define SB_B4   198656
#define SB_TBLW 198672
#define SB_TBLB 204816
#define SB_TBLP 210960
#define SMEM_BYTES 217104

__device__ __align__(128) float g_feat_nhwc[FEATTOT];

__global__ void __launch_bounds__(256) transpose_kernel(const float* __restrict__ f) {
    int idx = blockIdx.x * 256 + threadIdx.x;
    if (idx >= FEATTOT) return;
    int c = idx & 127;
    int rest = idx >> 7;
    int w = rest % W_;
    int r2 = rest / W_;
    int h = r2 % H_;
    int b = r2 / H_;
    g_feat_nhwc[idx] = f[((b * 128 + c) * H_ + h) * W_ + w];
}

__device__ __forceinline__ unsigned smem_u32(const void* p) {
    unsigned a;
    asm("{ .reg .u64 t; cvta.to.shared.u64 t, %1; cvt.u32.u64 %0, t; }" : "=r"(a) : "l"(p));
    return a;
}
__device__ __forceinline__ void ldsm4(unsigned& r0, unsigned& r1, unsigned& r2, unsigned& r3,
                                      unsigned addr) {
    asm volatile("ldmatrix.sync.aligned.m8n8.x4.shared.b16 {%0,%1,%2,%3}, [%4];"
                 : "=r"(r0), "=r"(r1), "=r"(r2), "=r"(r3) : "r"(addr));
}
__device__ __forceinline__ void mma16816(float* c, unsigned a0, unsigned a1, unsigned a2,
                                         unsigned a3, unsigned b0, unsigned b1) {
    asm volatile("mma.sync.aligned.m16n8k16.row.col.f32.bf16.bf16.f32 "
                 "{%0,%1,%2,%3}, {%4,%5,%6,%7}, {%8,%9}, {%0,%1,%2,%3};"
                 : "+f"(c[0]), "+f"(c[1]), "+f"(c[2]), "+f"(c[3])
                 : "r"(a0), "r"(a1), "r"(a2), "r"(a3), "r"(b0), "r"(b1));
}
__device__ __forceinline__ void split2(float a, float b, unsigned& hi, unsigned& lo) {
    __nv_bfloat16 ha = __float2bfloat16(a), hb = __float2bfloat16(b);
    __nv_bfloat162 hp(ha, hb);
    __nv_bfloat162 lp(__float2bfloat16(a - __bfloat162float(ha)),
                      __float2bfloat16(b - __bfloat162float(hb)));
    hi = *(unsigned*)&hp;
    lo = *(unsigned*)&lp;
}
__device__ __forceinline__ void initc2(float (*c0)[4], float (*c1)[4],
                                       const float* bias, int lane) {
    int cq = (lane & 3) * 2;
    #pragma unroll
    for (int j = 0; j < 8; j++) {
        float v0 = bias[j*8 + cq], v1 = bias[j*8 + cq + 1];
        c0[j][0] = v0; c0[j][1] = v1; c0[j][2] = v0; c0[j][3] = v1;
        c1[j][0] = v0; c1[j][1] = v1; c1[j][2] = v0; c1[j][3] = v1;
    }
}

// M=32 GEMM, K=64: A (32x64 bf16, 128B rows, chunk^row swizzle) @ B^T.
// B k-chunk bases: kc 0,1 use kb0, kc 2,3 use kb1 (k units, multiple of 32).
// brsLog: log2 of B row stride bytes (9 for W1, 7 for W2/W3).
__device__ __forceinline__ void gemm_m32(
    float (*c0)[4], float (*c1)[4],
    unsigned aHiA, unsigned aLoA, unsigned bHiA, unsigned bLoA,
    int brsLog, int kb0, int kb1, int lane)
{
    int r = lane & 15, kh = lane >> 4;
    int l7 = lane & 7, mat = lane >> 3;
    int khb = mat & 1, jup = (mat >> 1) & 1;
    #pragma unroll
    for (int kc = 0; kc < 4; kc++) {
        unsigned ac = (unsigned)(kc*2 + kh);
        unsigned aoff = (unsigned)(r*128) + ((ac ^ (unsigned)(r & 7)) * 16u);
        unsigned p0h0, p0h1, p0h2, p0h3, p0l0, p0l1, p0l2, p0l3;
        unsigned p1h0, p1h1, p1h2, p1h3, p1l0, p1l1, p1l2, p1l3;
        ldsm4(p0h0, p0h1, p0h2, p0h3, aHiA + aoff);
        ldsm4(p0l0, p0l1, p0l2, p0l3, aLoA + aoff);
        ldsm4(p1h0, p1h1, p1h2, p1h3, aHiA + aoff + 2048u);
        ldsm4(p1l0, p1l1, p1l2, p1l3, aLoA + aoff + 2048u);
        int kbase = (kc < 2) ? kb0 : kb1;
        unsigned bc = (unsigned)((kbase >> 3) + (kc & 1) * 2 + khb);
        #pragma unroll
        for (int jp = 0; jp < 4; jp++) {
            unsigned n = (unsigned)(((jp*2 + jup) << 3) + l7);
            unsigned boff = (n << brsLog) + ((bc ^ (n & 7u)) * 16u);
            unsigned bh0, bh1, bh2, bh3, bl0, bl1, bl2, bl3;
            ldsm4(bh0, bh1, bh2, bh3, bHiA + boff);
            ldsm4(bl0, bl1, bl2, bl3, bLoA + boff);
            mma16816(c0[jp*2],   p0h0, p0h1, p0h2, p0h3, bh0, bh1);
            mma16816(c0[jp*2],   p0l0, p0l1, p0l2, p0l3, bh0, bh1);
            mma16816(c0[jp*2],   p0h0, p0h1, p0h2, p0h3, bl0, bl1);
            mma16816(c0[jp*2+1], p0h0, p0h1, p0h2, p0h3, bh2, bh3);
            mma16816(c0[jp*2+1], p0l0, p0l1, p0l2, p0l3, bh2, bh3);
            mma16816(c0[jp*2+1], p0h0, p0h1, p0h2, p0h3, bl2, bl3);
            mma16816(c1[jp*2],   p1h0, p1h1, p1h2, p1h3, bh0, bh1);
            mma16816(c1[jp*2],   p1l0, p1l1, p1l2, p1l3, bh0, bh1);
            mma16816(c1[jp*2],   p1h0, p1h1, p1h2, p1h3, bl0, bl1);
            mma16816(c1[jp*2+1], p1h0, p1h1, p1h2, p1h3, bh2, bh3);
            mma16816(c1[jp*2+1], p1l0, p1l1, p1l2, p1l3, bh2, bh3);
            mma16816(c1[jp*2+1], p1h0, p1h1, p1h2, p1h3, bl2, bl3);
        }
    }
}

// relu + split + store one m16 C tile into A rows [mt*16, mt*16+16)
__device__ __forceinline__ void relu_store_A(float (*c)[4], char* sc,
                                             unsigned aHiOff, unsigned aLoOff,
                                             int mt, int lane) {
    int r = lane >> 2, sub = (lane & 3) * 4;
    int row0 = mt*16 + r, row1 = row0 + 8;
    unsigned key = (unsigned)(row0 & 7);
    #pragma unroll
    for (int j = 0; j < 8; j++) {
        float v0 = fmaxf(c[j][0], 0.f), v1 = fmaxf(c[j][1], 0.f);
        float v2 = fmaxf(c[j][2], 0.f), v3 = fmaxf(c[j][3], 0.f);
        unsigned h01, l01, h23, l23;
        split2(v0, v1, h01, l01);
        split2(v2, v3, h23, l23);
        unsigned off0 = (unsigned)(row0*128) + (((unsigned)j ^ key) * 16u) + (unsigned)sub;
        unsigned off1 = (unsigned)(row1*128) + (((unsigned)j ^ key) * 16u) + (unsigned)sub;
        *(unsigned*)(sc + aHiOff + off0) = h01;
        *(unsigned*)(sc + aLoOff + off0) = l01;
        *(unsigned*)(sc + aHiOff + off1) = h23;
        *(unsigned*)(sc + aLoOff + off1) = l23;
    }
}

__global__ void __launch_bounds__(BD) decoder_kernel(
    const float* __restrict__ points, const float* __restrict__ kmat,
    const float* __restrict__ rt, const float* __restrict__ Bg,
    const float* __restrict__ W1, const float* __restrict__ b1,
    const float* __restrict__ W2, const float* __restrict__ b2,
    const float* __restrict__ W3, const float* __restrict__ b3,
    const float* __restrict__ W4, const float* __restrict__ b4,
    float* __restrict__ out)
{
    extern __shared__ __align__(16) char sc[];
    unsigned sb = smem_u32(sc);
    int tid = threadIdx.x;
    int lane = tid & 31, wid = tid >> 5;

    // ---- stage weights [n][k] k-contiguous, hi/lo bf16, chunk^n swizzle ----
    for (int t = tid; t < 16384; t += BD) {
        int k = t >> 6, n = t & 63;
        float v = W1[t];
        __nv_bfloat16 hv = __float2bfloat16(v);
        unsigned off = (unsigned)(n*512) + ((((unsigned)(k >> 3)) ^ (unsigned)(n & 7)) * 16u)
                     + (unsigned)((k & 7) * 2);
        *(__nv_bfloat16*)(sc + SB_W1HI + off) = hv;
        *(__nv_bfloat16*)(sc + SB_W1LO + off) = __float2bfloat16(v - __bfloat162float(hv));
    }
    for (int t = tid; t < 4096; t += BD) {
        int k = t >> 6, n = t & 63;
        unsigned off = (unsigned)(n*128) + ((((unsigned)(k >> 3)) ^ (unsigned)(n & 7)) * 16u)
                     + (unsigned)((k & 7) * 2);
        float v2 = W2[t];
        __nv_bfloat16 h2 = __float2bfloat16(v2);
        *(__nv_bfloat16*)(sc + SB_W2HI + off) = h2;
        *(__nv_bfloat16*)(sc + SB_W2LO + off) = __float2bfloat16(v2 - __bfloat162float(h2));
        float v3 = W3[t];
        __nv_bfloat16 h3 = __float2bfloat16(v3);
        *(__nv_bfloat16*)(sc + SB_W3HI + off) = h3;
        *(__nv_bfloat16*)(sc + SB_W3LO + off) = __float2bfloat16(v3 - __bfloat162float(h3));
    }
    if (tid < 64) {
        ((float*)(sc + SB_B1))[tid] = b1[tid];
        ((float*)(sc + SB_B2))[tid] = b2[tid];
        ((float*)(sc + SB_B3))[tid] = b3[tid];
        ((float*)(sc + SB_W4))[tid] = W4[tid];
        ((float*)(sc + SB_BG))[tid*4 + 0] = Bg[tid*3 + 0];
        ((float*)(sc + SB_BG))[tid*4 + 1] = Bg[tid*3 + 1];
        ((float*)(sc + SB_BG))[tid*4 + 2] = Bg[tid*3 + 2];
        ((float*)(sc + SB_BG))[tid*4 + 3] = 0.0f;
    }
    if (tid == 0) *(float*)(sc + SB_B4) = b4[0];
    __syncthreads();

    const float* b1p = (const float*)(sc + SB_B1);
    const float* b2p = (const float*)(sc + SB_B2);
    const float* b3p = (const float*)(sc + SB_B3);
    const float* w4p = (const float*)(sc + SB_W4);
    float b4v = *(const float*)(sc + SB_B4);

    unsigned aHiOff = SB_A1HI + (unsigned)(wid * 4096);
    unsigned aLoOff = SB_A1LO + (unsigned)(wid * 4096);
    unsigned aHiA = sb + aHiOff, aLoA = sb + aLoOff;
    unsigned twOff = SB_TBLW + (unsigned)(wid * 512);
    unsigned tbOff = SB_TBLB + (unsigned)(wid * 512);
    unsigned tpOff = SB_TBLP + (unsigned)(wid * 512);

    int half = lane >> 4, l15 = lane & 15;

    for (int tile = blockIdx.x; tile < NT; tile += GRID_DEC) {
        int p0 = tile * TILE_PTS + wid * 32;

        // ---- 1. projection: 32 lanes, one point each ----
        {
            int pidx = min(p0 + lane, TOTPTS - 1);
            int b = pidx >> 16;
            float px = points[pidx*3 + 0];
            float py = points[pidx*3 + 1];
            float pz = points[pidx*3 + 2];
            const float* rtb = rt + b*12;
            const float* kb  = kmat + b*9;
            float c0 = rtb[0]*px + rtb[1]*py + rtb[2]*pz + rtb[3];
            float c1 = rtb[4]*px + rtb[5]*py + rtb[6]*pz + rtb[7];
            float c2 = rtb[8]*px + rtb[9]*py + rtb[10]*pz + rtb[11];
            float i0 = kb[0]*c0 + kb[1]*c1 + kb[2]*c2;
            float i1 = kb[3]*c0 + kb[4]*c1 + kb[5]*c2;
            float i2 = kb[6]*c0 + kb[7]*c1 + kb[8]*c2;
            float zb = i2 + 1e-8f;
            float u = i0 / zb, v = i1 / zb;
            float validf = (i2 > 0.0f) ? 1.0f : 0.0f;
            float un = (2.0f*u + 1.0f) / 56.0f - 1.0f;
            float vn = (2.0f*v + 1.0f) / 56.0f - 1.0f;
            float xp = ((un + 1.0f) * 56.0f - 1.0f) * 0.5f;
            float yp = ((vn + 1.0f) * 56.0f - 1.0f) * 0.5f;
            float x0f = floorf(xp), y0f = floorf(yp);
            float fx = xp - x0f, fy = yp - y0f;
            float gx0 = 1.0f - fx, gy0 = 1.0f - fy;
            int ix0 = (int)x0f, iy0 = (int)y0f;
            int ix1 = ix0 + 1, iy1 = iy0 + 1;
            float m00 = (ix0 >= 0 && ix0 < W_ && iy0 >= 0 && iy0 < H_) ? validf : 0.0f;
            float m10 = (ix1 >= 0 && ix1 < W_ && iy0 >= 0 && iy0 < H_) ? validf : 0.0f;
            float m01 = (ix0 >= 0 && ix0 < W_ && iy1 >= 0 && iy1 < H_) ? validf : 0.0f;
            float m11 = (ix1 >= 0 && ix1 < W_ && iy1 >= 0 && iy1 < H_) ? validf : 0.0f;
            int cx0 = min(max(ix0, 0), W_-1), cx1 = min(max(ix1, 0), W_-1);
            int cy0 = min(max(iy0, 0), H_-1), cy1 = min(max(iy1, 0), H_-1);
            *(float4*)(sc + twOff + lane*16) =
                make_float4(gx0*gy0*m00, fx*gy0*m10, gx0*fy*m01, fx*fy*m11);
            *(int4*)(sc + tbOff + lane*16) =
                make_int4(((b*H_ + cy0)*W_ + cx0) << 7, ((b*H_ + cy0)*W_ + cx1) << 7,
                          ((b*H_ + cy1)*W_ + cx0) << 7, ((b*H_ + cy1)*W_ + cx1) << 7);
            *(float4*)(sc + tpOff + lane*16) = make_float4(px, py, pz, 0.0f);
        }
        __syncwarp();

        float c0[8][4], c1[8][4];
        initc2(c0, c1, b1p, lane);

        // ---- layer 1: 4 K=64 passes ----
        #pragma unroll 1
        for (int pass = 0; pass < 4; pass++) {
            if (pass < 2) {
                // image features, channels pass*64 .. pass*64+63
                int chunkC = l15 >> 1, sub8 = (l15 & 1) * 8;
                #pragma unroll 2
                for (int it = 0; it < 16; it++) {
                    int p = it*2 + half;
                    float4 wv = *(const float4*)(sc + twOff + p*16);
                    int4 bv = *(const int4*)(sc + tbOff + p*16);
                    int goff = pass*64 + l15*4;
                    float4 v0 = *(const float4*)(g_feat_nhwc + bv.x + goff);
                    float4 v1 = *(const float4*)(g_feat_nhwc + bv.y + goff);
                    float4 v2 = *(const float4*)(g_feat_nhwc + bv.z + goff);
                    float4 v3 = *(const float4*)(g_feat_nhwc + bv.w + goff);
                    float a0 = wv.x*v0.x + wv.y*v1.x + wv.z*v2.x + wv.w*v3.x;
                    float a1 = wv.x*v0.y + wv.y*v1.y + wv.z*v2.y + wv.w*v3.y;
                    float a2 = wv.x*v0.z + wv.y*v1.z + wv.z*v2.z + wv.w*v3.z;
                    float a3 = wv.x*v0.w + wv.y*v1.w + wv.z*v2.w + wv.w*v3.w;
                    unsigned h01, l01, h23, l23;
                    split2(a0, a1, h01, l01);
                    split2(a2, a3, h23, l23);
                    unsigned off = (unsigned)(p*128 + ((chunkC ^ (p & 7)) * 16) + sub8);
                    *(uint2*)(sc + aHiOff + off) = make_uint2(h01, h23);
                    *(uint2*)(sc + aLoOff + off) = make_uint2(l01, l23);
                }
            } else {
                // fourier: pass2 m 0..31, pass3 m 32..63; sin -> k 0..31, cos -> k 32..63
                int mbase = (pass - 2) * 32 + (l15 << 1);
                #pragma unroll 2
                for (int it = 0; it < 16; it++) {
                    int p = it*2 + half;
                    float4 pc = *(const float4*)(sc + tpOff + p*16);
                    float4 bg0 = *(const float4*)(sc + SB_BG + mbase*16);
                    float4 bg1 = *(const float4*)(sc + SB_BG + mbase*16 + 16);
                    float s0, cc0, s1, cc1;
                    sincosf(TWOPI * (pc.x*bg0.x + pc.y*bg0.y + pc.z*bg0.z), &s0, &cc0);
                    sincosf(TWOPI * (pc.x*bg1.x + pc.y*bg1.y + pc.z*bg1.z), &s1, &cc1);
                    unsigned sh, sl, ch, cl;
                    split2(s0, s1, sh, sl);
                    split2(cc0, cc1, ch, cl);
                    unsigned key = (unsigned)(p & 7);
                    unsigned offS = (unsigned)(p*128) + ((((unsigned)(l15 >> 2)) ^ key) * 16u)
                                  + (unsigned)((l15 & 3) * 4);
                    unsigned offC = (unsigned)(p*128) + ((((unsigned)((l15 >> 2) + 4)) ^ key) * 16u)
                                  + (unsigned)((l15 & 3) * 4);
                    *(unsigned*)(sc + aHiOff + offS) = sh;
                    *(unsigned*)(sc + aLoOff + offS) = sl;
                    *(unsigned*)(sc + aHiOff + offC) = ch;
                    *(unsigned*)(sc + aLoOff + offC) = cl;
                }
            }
            __syncwarp();
            int kb0, kb1;
            if (pass == 0)      { kb0 = 0;   kb1 = 32;  }
            else if (pass == 1) { kb0 = 64;  kb1 = 96;  }
            else if (pass == 2) { kb0 = 128; kb1 = 192; }
            else                { kb0 = 160; kb1 = 224; }
            gemm_m32(c0, c1, aHiA, aLoA, sb + SB_W1HI, sb + SB_W1LO, 9, kb0, kb1, lane);
            __syncwarp();
        }

        // ---- epilogue 1 -> A2, layer 2 ----
        relu_store_A(c0, sc, aHiOff, aLoOff, 0, lane);
        relu_store_A(c1, sc, aHiOff, aLoOff, 1, lane);
        __syncwarp();
        initc2(c0, c1, b2p, lane);
        gemm_m32(c0, c1, aHiA, aLoA, sb + SB_W2HI, sb + SB_W2LO, 7, 0, 32, lane);
        __syncwarp();

        // ---- epilogue 2 -> A2, layer 3 ----
        relu_store_A(c0, sc, aHiOff, aLoOff, 0, lane);
        relu_store_A(c1, sc, aHiOff, aLoOff, 1, lane);
        __syncwarp();
        initc2(c0, c1, b3p, lane);
        gemm_m32(c0, c1, aHiA, aLoA, sb + SB_W3HI, sb + SB_W3LO, 7, 0, 32, lane);

        // ---- layer 4: dot(relu(h3), W4) + b4 ----
        {
            int r = lane >> 2, cq = (lane & 3) * 2;
            #pragma unroll
            for (int mt = 0; mt < 2; mt++) {
                float (*cf)[4] = (mt == 0) ? c0 : c1;
                float o0 = 0.f, o1 = 0.f;
                #pragma unroll
                for (int j = 0; j < 8; j++) {
                    int col = j*8 + cq;
                    float wa = w4p[col], wb = w4p[col + 1];
                    o0 += fmaxf(cf[j][0], 0.f) * wa + fmaxf(cf[j][1], 0.f) * wb;
                    o1 += fmaxf(cf[j][2], 0.f) * wa + fmaxf(cf[j][3], 0.f) * wb;
                }
                o0 += __shfl_xor_sync(0xFFFFFFFFu, o0, 1);
                o0 += __shfl_xor_sync(0xFFFFFFFFu, o0, 2);
                o1 += __shfl_xor_sync(0xFFFFFFFFu, o1, 1);
                o1 += __shfl_xor_sync(0xFFFFFFFFu, o1, 2);
                if ((lane & 3) == 0) {
                    int pr = p0 + mt*16 + r;
                    if (pr < TOTPTS)     out[pr]     = o0 + b4v;
                    if (pr + 8 < TOTPTS) out[pr + 8] = o1 + b4v;
                }
            }
        }
        __syncwarp();
    }
}

extern "C" void kernel_launch(void* const* d_in, const int* in_sizes, int n_in,
                              void* d_out, int out_size) {
    const float* features = (const float*)d_in[0];
    const float* points   = (const float*)d_in[1];
    const float* kmat     = (const float*)d_in[2];
    const float* rt       = (const float*)d_in[3];
    const float* Bg       = (const float*)d_in[4];
    const float* W1       = (const float*)d_in[5];
    const float* b1       = (const float*)d_in[6];
    const float* W2       = (const float*)d_in[7];
    const float* b2       = (const float*)d_in[8];
    const float* W3       = (const float*)d_in[9];
    const float* b3       = (const float*)d_in[10];
    const float* W4       = (const float*)d_in[11];
    const float* b4       = (const float*)d_in[12];
    float* out = (float*)d_out;

    transpose_kernel<<<FEATTOT/256, 256>>>(features);

    cudaFuncSetAttribute(decoder_kernel,
                         cudaFuncAttributeMaxDynamicSharedMemorySize, SMEM_BYTES);
    decoder_kernel<<<GRID_DEC, BD, SMEM_BYTES>>>(
        points, kmat, rt, Bg, W1, b1, W2, b2, W3, b3, W4, b4, out);
}